// round 10
// baseline (speedup 1.0000x reference)
#include <cuda_runtime.h>

#define NT 128
#define BB 256
#define SS 512

__device__ double g_acc;
__device__ int    g_tags_is64;

__global__ void zero_acc_kernel(){ g_acc = 0.0; }
__global__ void fin_kernel(float* out){ out[0] = (float)g_acc; }

__device__ __forceinline__ unsigned long long pack2(float x, float y){
    unsigned long long u;
    asm("mov.b64 %0, {%1,%2};" : "=l"(u) : "f"(x), "f"(y));
    return u;
}
__device__ __forceinline__ void unpack2(unsigned long long u, float& x, float& y){
    asm("mov.b64 {%0,%1}, %2;" : "=f"(x), "=f"(y) : "l"(u));
}
__device__ __forceinline__ unsigned long long fma2(unsigned long long a,
                                                   unsigned long long b,
                                                   unsigned long long c){
    unsigned long long d;
    asm("fma.rn.f32x2 %0, %1, %2, %3;" : "=l"(d) : "l"(a), "l"(b), "l"(c));
    return d;
}
__device__ __forceinline__ unsigned long long add2(unsigned long long a,
                                                   unsigned long long b){
    unsigned long long d;
    asm("add.rn.f32x2 %0, %1, %2;" : "=l"(d) : "l"(a), "l"(b));
    return d;
}

// Detect tags dtype: if int64, all high words of valid tags (0..127) are zero.
__global__ void detect_tags_kernel(const int* tags32){
    __shared__ int nz;
    if (threadIdx.x == 0) nz = 0;
    __syncthreads();
    int c = 0;
    for (int k = threadIdx.x; k < 2048; k += 256)
        if (tags32[2 * k + 1] != 0) c = 1;
    if (c) atomicOr(&nz, 1);
    __syncthreads();
    if (threadIdx.x == 0) g_tags_is64 = (nz == 0) ? 1 : 0;
}

__global__ void __launch_bounds__(256) gold_kernel(
    const float* __restrict__ emis, const void* __restrict__ tags_raw,
    const unsigned char* __restrict__ mask, const float* __restrict__ trans)
{
    const int idx = blockIdx.x * 256 + threadIdx.x;
    const int t = idx & (SS - 1);
    const int is64 = g_tags_is64;
    const int* t32 = (const int*)tags_raw;
    const long long* t64 = (const long long*)tags_raw;

    const int tg = is64 ? (int)t64[idx] : t32[idx];
    const float m = mask[idx] ? 1.f : 0.f;
    float v = emis[(size_t)idx * NT + tg] * m;
    if (t > 0){
        const int tp = is64 ? (int)t64[idx - 1] : t32[idx - 1];
        v += trans[tp * NT + tg] * m;
    }
    #pragma unroll
    for (int off = 16; off >= 1; off >>= 1)
        v += __shfl_xor_sync(0xffffffffu, v, off);
    if ((threadIdx.x & 31) == 0)
        atomicAdd(&g_acc, -(double)v);
}

// Forward scan, linear domain + exact periodic rescale.
// 128 blocks x 512 threads; block handles 2 chains packed in f32x2 lanes.
// tid = j*4 + s: tag j (0..127), segment s (0..3) covers i in [32s, 32s+32).
// Segments of one tag sit in lanes {4q..4q+3} -> reduce via shfl_xor 1,2.
// Shared alpha padded: segment stride 34 float2 (272B) -> LDS.128 conflict-free.
#define SEG_STRIDE 34
__global__ void __launch_bounds__(512, 1) crf_forward(
    const float* __restrict__ emis, const float* __restrict__ trans)
{
    __shared__ __align__(16) float2 alpha[2][4 * SEG_STRIDE];
    __shared__ __align__(16) float2 wmax[16];

    const int tid  = threadIdx.x;
    const int j    = tid >> 2;
    const int s    = tid & 3;
    const int w    = tid >> 5;
    const int lane = tid & 31;
    const bool s0  = (s == 0);
    const int b0   = blockIdx.x * 2;

    // exp(T[i][j]) for this thread's 32-term segment, duplicated into f32x2
    unsigned long long eT[32];
    #pragma unroll
    for (int k = 0; k < 32; k++){
        const float e = __expf(trans[(s * 32 + k) * NT + j]);
        eT[k] = pack2(e, e);
    }

    const float* eb0 = emis + (size_t)b0 * SS * NT + j;
    const float* eb1 = eb0 + (size_t)SS * NT;

    // t = 0 init (writer lanes only)
    float eraw0 = 0.f, eraw1 = 0.f;
    if (s0){
        const float a0 = __expf(eb0[0]);
        const float a1 = __expf(eb1[0]);
        alpha[0][(j >> 5) * SEG_STRIDE + (j & 31)] = make_float2(a0, a1);
        float mx0 = a0, mx1 = a1;
        #pragma unroll
        for (int off = 4; off <= 16; off <<= 1){
            mx0 = fmaxf(mx0, __shfl_xor_sync(0x11111111u, mx0, off));
            mx1 = fmaxf(mx1, __shfl_xor_sync(0x11111111u, mx1, off));
        }
        if (lane == 0) wmax[w] = make_float2(mx0, mx1);
        eraw0 = eb0[NT];                 // prefetch t = 1
        eraw1 = eb1[NT];
    }
    __syncthreads();

    float lz0 = 0.f, lz1 = 0.f;          // tracked by tid 0 only

    #pragma unroll 4
    for (int t = 1; t < SS; t++){
        const int p = t & 1;

        // 32-term segment dot, f32x2, 4 chains of depth 8
        unsigned long long a0 = 0ull, a1 = 0ull, a2 = 0ull, a3 = 0ull;
        const ulonglong2* ap =
            (const ulonglong2*)(alpha[p ^ 1] + s * SEG_STRIDE);
        #pragma unroll
        for (int k = 0; k < 8; k++){
            const ulonglong2 u = ap[k];
            const ulonglong2 v = ap[k + 8];
            a0 = fma2(u.x, eT[2 * k],      a0);
            a1 = fma2(u.y, eT[2 * k + 1],  a1);
            a2 = fma2(v.x, eT[2 * k + 16], a2);
            a3 = fma2(v.y, eT[2 * k + 17], a3);
        }
        float r0, r1;
        unpack2(add2(add2(a0, a1), add2(a2, a3)), r0, r1);

        // sum the 4 segments (lanes differing in bits 0..1)
        r0 += __shfl_xor_sync(0xffffffffu, r0, 1);
        r1 += __shfl_xor_sync(0xffffffffu, r1, 1);
        r0 += __shfl_xor_sync(0xffffffffu, r0, 2);
        r1 += __shfl_xor_sync(0xffffffffu, r1, 2);

        if (s0){
            // consume rescale max produced at step t-1 when (t-1)%4 == 0
            float inv0 = 1.f, inv1 = 1.f;
            if (((t - 1) & 3) == 0){
                const float4* wm = (const float4*)wmax;
                float m0 = 0.f, m1 = 0.f;
                #pragma unroll
                for (int r = 0; r < 8; r++){
                    const float4 q = wm[r];
                    m0 = fmaxf(m0, fmaxf(q.x, q.z));
                    m1 = fmaxf(m1, fmaxf(q.y, q.w));
                }
                inv0 = 1.0f / m0;
                inv1 = 1.0f / m1;
                if (tid == 0){ lz0 += logf(m0); lz1 += logf(m1); }
            }

            const float v0 = r0 * inv0 * __expf(eraw0);
            const float v1 = r1 * inv1 * __expf(eraw1);

            // produce max for the rescale at step t+1
            if ((t & 3) == 0){
                float mx0 = v0, mx1 = v1;
                #pragma unroll
                for (int off = 4; off <= 16; off <<= 1){
                    mx0 = fmaxf(mx0, __shfl_xor_sync(0x11111111u, mx0, off));
                    mx1 = fmaxf(mx1, __shfl_xor_sync(0x11111111u, mx1, off));
                }
                if (lane == 0) wmax[w] = make_float2(mx0, mx1);
            }

            alpha[p][(j >> 5) * SEG_STRIDE + (j & 31)] = make_float2(v0, v1);

            // prefetch next step's raw emissions
            const int tt = (t + 1 < SS) ? (t + 1) : (SS - 1);
            eraw0 = eb0[(size_t)tt * NT];
            eraw1 = eb1[(size_t)tt * NT];
        }
        __syncthreads();
    }

    if (tid == 0){
        double p0 = 0.0, p1 = 0.0;
        for (int i = 0; i < NT; i++){
            const float2 v = alpha[1][(i >> 5) * SEG_STRIDE + (i & 31)];
            p0 += (double)v.x; p1 += (double)v.y;
        }
        atomicAdd(&g_acc, (log(p0) + (double)lz0) + (log(p1) + (double)lz1));
    }
}

extern "C" void kernel_launch(void* const* d_in, const int* in_sizes, int n_in,
                              void* d_out, int out_size)
{
    const float*         emis  = (const float*)d_in[0];
    const void*          tags  = d_in[1];
    const unsigned char* mask  = (const unsigned char*)d_in[2];
    const float*         trans = (const float*)d_in[3];

    zero_acc_kernel<<<1, 1>>>();
    detect_tags_kernel<<<1, 256>>>((const int*)tags);
    gold_kernel<<<(BB * SS) / 256, 256>>>(emis, tags, mask, trans);
    crf_forward<<<BB / 2, 512>>>(emis, trans);
    fin_kernel<<<1, 1>>>((float*)d_out);
}

// round 12
// speedup vs baseline: 1.0673x; 1.0673x over previous
#include <cuda_runtime.h>

#define NT 128
#define BB 256
#define SS 512

__device__ double g_acc;
__device__ int    g_tags_is64;

__global__ void zero_acc_kernel(){ g_acc = 0.0; }
__global__ void fin_kernel(float* out){ out[0] = (float)g_acc; }

// Detect tags dtype: if int64, all high words of valid tags (0..127) are zero.
__global__ void detect_tags_kernel(const int* tags32){
    __shared__ int nz;
    if (threadIdx.x == 0) nz = 0;
    __syncthreads();
    int c = 0;
    for (int k = threadIdx.x; k < 2048; k += 256)
        if (tags32[2 * k + 1] != 0) c = 1;
    if (c) atomicOr(&nz, 1);
    __syncthreads();
    if (threadIdx.x == 0) g_tags_is64 = (nz == 0) ? 1 : 0;
}

__global__ void __launch_bounds__(256) gold_kernel(
    const float* __restrict__ emis, const void* __restrict__ tags_raw,
    const unsigned char* __restrict__ mask, const float* __restrict__ trans)
{
    const int idx = blockIdx.x * 256 + threadIdx.x;
    const int t = idx & (SS - 1);
    const int is64 = g_tags_is64;
    const int* t32 = (const int*)tags_raw;
    const long long* t64 = (const long long*)tags_raw;

    const int tg = is64 ? (int)t64[idx] : t32[idx];
    const float m = mask[idx] ? 1.f : 0.f;
    float v = emis[(size_t)idx * NT + tg] * m;
    if (t > 0){
        const int tp = is64 ? (int)t64[idx - 1] : t32[idx - 1];
        v += trans[tp * NT + tg] * m;
    }
    #pragma unroll
    for (int off = 16; off >= 1; off >>= 1)
        v += __shfl_xor_sync(0xffffffffu, v, off);
    if ((threadIdx.x & 31) == 0)
        atomicAdd(&g_acc, -(double)v);
}

// Forward scan, linear domain + exact periodic rescale.
// 128 blocks x 512 threads. Block = 2 chains (h). tid = h*256 + j*2 + s:
// tag j (0..127), dot-half s (0..1) covers i in [64s, 64s+64).
// s is the lane LSB -> combine with ONE shfl_xor(1); after it BOTH lanes hold
// the full sum, so the epilogue is uniform across the warp (no divergence).
// alpha halves padded apart by 68 floats so the warp's two s-address streams
// hit disjoint 4-bank groups (LDS.128 conflict-free).
#define HPAD 68
__device__ __forceinline__ int aidx(int i){ return i + ((i >> 6) << 2); } // i + 4*(i>=64)

__global__ void __launch_bounds__(512, 1) crf_forward(
    const float* __restrict__ emis, const float* __restrict__ trans)
{
    __shared__ __align__(16) float alpha[2][2][2 * HPAD];  // [parity][h][padded 128]
    __shared__ float wmax[16];                              // per-warp maxes

    const int tid  = threadIdx.x;
    const int h    = tid >> 8;
    const int j    = (tid >> 1) & 127;
    const int s    = tid & 1;
    const int w    = tid >> 5;
    const int lane = tid & 31;
    const int b    = blockIdx.x * 2 + h;

    // exp(T[i][j]) for this thread's 64-term half, in registers
    float eT[64];
    #pragma unroll
    for (int k = 0; k < 64; k++)
        eT[k] = __expf(trans[(s * 64 + k) * NT + j]);

    const float* eb = emis + (size_t)b * SS * NT + j;

    // t = 0 init
    const float a0 = __expf(eb[0]);
    if (s == 0) alpha[0][h][aidx(j)] = a0;
    {
        float mx = a0;
        #pragma unroll
        for (int off = 16; off >= 1; off >>= 1)
            mx = fmaxf(mx, __shfl_xor_sync(0xffffffffu, mx, off));
        if (lane == 0) wmax[w] = mx;
    }
    float eraw = eb[NT];                 // prefetch t = 1
    __syncthreads();

    float lz = 0.f;                      // meaningful on tid 0 (h0) / tid 256 (h1)

    #pragma unroll 4
    for (int t = 1; t < SS; t++){
        const int p = t & 1;

        // emission exp off the critical path, then prefetch next step
        const float eexp = __expf(eraw);
        if (t + 1 < SS) eraw = eb[(size_t)(t + 1) * NT];

        // 64-term half-dot, 4 ILP chains of depth 16
        float c0 = 0.f, c1 = 0.f, c2 = 0.f, c3 = 0.f;
        const float4* ap = (const float4*)(alpha[p ^ 1][h] + s * HPAD);
        #pragma unroll
        for (int k = 0; k < 16; k++){
            const float4 a = ap[k];
            c0 = fmaf(a.x, eT[4 * k + 0], c0);
            c1 = fmaf(a.y, eT[4 * k + 1], c1);
            c2 = fmaf(a.z, eT[4 * k + 2], c2);
            c3 = fmaf(a.w, eT[4 * k + 3], c3);
        }
        float r = (c0 + c1) + (c2 + c3);
        r += __shfl_xor_sync(0xffffffffu, r, 1);   // both lanes now hold full dot

        // consume rescale max produced at step t-1 when (t-1)%4 == 0
        float inv = 1.f;
        if (((t - 1) & 3) == 0){
            const float4* wm = (const float4*)(wmax + 8 * h);
            const float4 q0 = wm[0], q1 = wm[1];
            const float m = fmaxf(fmaxf(fmaxf(q0.x, q0.y), fmaxf(q0.z, q0.w)),
                                  fmaxf(fmaxf(q1.x, q1.y), fmaxf(q1.z, q1.w)));
            inv = 1.0f / m;
            if ((tid & 255) == 0) lz += logf(m);
        }

        const float v = r * inv * eexp;

        // produce max for the rescale at step t+1 (uniform warp reduce; the
        // duplicated pair values don't change the max)
        if ((t & 3) == 0){
            float mx = v;
            #pragma unroll
            for (int off = 16; off >= 1; off >>= 1)
                mx = fmaxf(mx, __shfl_xor_sync(0xffffffffu, mx, off));
            if (lane == 0) wmax[w] = mx;
        }

        if (s == 0) alpha[p][h][aidx(j)] = v;     // single predicated STS
        __syncthreads();
    }

    // partition: log(sum_j alpha_511[j]) + lz, per chain half
    if ((tid & 255) == 0){
        double psum = 0.0;
        for (int i = 0; i < NT; i++)
            psum += (double)alpha[1][h][aidx(i)];  // last parity: 511 & 1 = 1
        atomicAdd(&g_acc, log(psum) + (double)lz);
    }
}

extern "C" void kernel_launch(void* const* d_in, const int* in_sizes, int n_in,
                              void* d_out, int out_size)
{
    const float*         emis  = (const float*)d_in[0];
    const void*          tags  = d_in[1];
    const unsigned char* mask  = (const unsigned char*)d_in[2];
    const float*         trans = (const float*)d_in[3];

    zero_acc_kernel<<<1, 1>>>();
    detect_tags_kernel<<<1, 256>>>((const int*)tags);
    gold_kernel<<<(BB * SS) / 256, 256>>>(emis, tags, mask, trans);
    crf_forward<<<BB / 2, 512>>>(emis, trans);
    fin_kernel<<<1, 1>>>((float*)d_out);
}

// round 13
// speedup vs baseline: 1.5788x; 1.4792x over previous
#include <cuda_runtime.h>

#define NT 128
#define BB 256
#define SS 512

__device__ double g_acc;
__device__ int    g_tags_is64;

__global__ void zero_acc_kernel(){ g_acc = 0.0; }
__global__ void fin_kernel(float* out){ out[0] = (float)g_acc; }

// Detect tags dtype: if int64, all high words of valid tags (0..127) are zero.
__global__ void detect_tags_kernel(const int* tags32){
    __shared__ int nz;
    if (threadIdx.x == 0) nz = 0;
    __syncthreads();
    int c = 0;
    for (int k = threadIdx.x; k < 2048; k += 256)
        if (tags32[2 * k + 1] != 0) c = 1;
    if (c) atomicOr(&nz, 1);
    __syncthreads();
    if (threadIdx.x == 0) g_tags_is64 = (nz == 0) ? 1 : 0;
}

__global__ void __launch_bounds__(256) gold_kernel(
    const float* __restrict__ emis, const void* __restrict__ tags_raw,
    const unsigned char* __restrict__ mask, const float* __restrict__ trans)
{
    const int idx = blockIdx.x * 256 + threadIdx.x;
    const int t = idx & (SS - 1);
    const int is64 = g_tags_is64;
    const int* t32 = (const int*)tags_raw;
    const long long* t64 = (const long long*)tags_raw;

    const int tg = is64 ? (int)t64[idx] : t32[idx];
    const float m = mask[idx] ? 1.f : 0.f;
    float v = emis[(size_t)idx * NT + tg] * m;
    if (t > 0){
        const int tp = is64 ? (int)t64[idx - 1] : t32[idx - 1];
        v += trans[tp * NT + tg] * m;
    }
    #pragma unroll
    for (int off = 16; off >= 1; off >>= 1)
        v += __shfl_xor_sync(0xffffffffu, v, off);
    if ((threadIdx.x & 31) == 0)
        atomicAdd(&g_acc, -(double)v);
}

// Forward scan, linear domain + exact periodic rescale.
// 128 blocks x 128 threads. Block = 2 chains; thread j (= tid) owns tag j of
// BOTH chains and computes both full 128-term dots (8 independent FMA chains
// -> one warp saturates its SMSP FMA pipe; no cross-thread dot reduction).
// eT (exp of transition column j) is shared by both chains.
__global__ void __launch_bounds__(128, 1) crf_forward(
    const float* __restrict__ emis, const float* __restrict__ trans)
{
    __shared__ __align__(16) float alpha[2][2][NT];  // [parity][chain][tag]
    __shared__ float wmax[2][4];                     // [chain][warp]

    const int j    = threadIdx.x;       // 0..127
    const int w    = j >> 5;            // warp 0..3
    const int lane = j & 31;
    const int b0   = blockIdx.x * 2;

    // register-cached exp(transitions) column j
    float eT[NT];
    #pragma unroll
    for (int i = 0; i < NT; i++)
        eT[i] = __expf(trans[i * NT + j]);

    const float* eb0 = emis + (size_t)b0 * SS * NT + j;
    const float* eb1 = eb0 + (size_t)SS * NT;

    // t = 0 init
    const float a00 = __expf(eb0[0]);
    const float a10 = __expf(eb1[0]);
    alpha[0][0][j] = a00;
    alpha[0][1][j] = a10;
    {
        float m0 = a00, m1 = a10;
        #pragma unroll
        for (int off = 16; off >= 1; off >>= 1){
            m0 = fmaxf(m0, __shfl_xor_sync(0xffffffffu, m0, off));
            m1 = fmaxf(m1, __shfl_xor_sync(0xffffffffu, m1, off));
        }
        if (lane == 0){ wmax[0][w] = m0; wmax[1][w] = m1; }
    }
    float eraw0 = eb0[NT];              // prefetch t = 1
    float eraw1 = eb1[NT];
    __syncthreads();

    float lz0 = 0.f, lz1 = 0.f;         // meaningful on tid 0

    for (int t = 1; t < SS; t++){
        const int p = t & 1;

        // emission exps off the critical path, then prefetch next step
        const float e0 = __expf(eraw0);
        const float e1 = __expf(eraw1);
        if (t + 1 < SS){
            eraw0 = eb0[(size_t)(t + 1) * NT];
            eraw1 = eb1[(size_t)(t + 1) * NT];
        }

        // both chains' full dots: 8 independent FMA chains of depth 16
        float c00 = 0.f, c01 = 0.f, c02 = 0.f, c03 = 0.f;
        float c10 = 0.f, c11 = 0.f, c12 = 0.f, c13 = 0.f;
        const float4* ap0 = (const float4*)alpha[p ^ 1][0];  // broadcast reads
        const float4* ap1 = (const float4*)alpha[p ^ 1][1];
        #pragma unroll
        for (int k = 0; k < NT / 4; k++){
            const float4 a = ap0[k];
            const float4 bq = ap1[k];
            c00 = fmaf(a.x,  eT[4 * k + 0], c00);
            c01 = fmaf(a.y,  eT[4 * k + 1], c01);
            c02 = fmaf(a.z,  eT[4 * k + 2], c02);
            c03 = fmaf(a.w,  eT[4 * k + 3], c03);
            c10 = fmaf(bq.x, eT[4 * k + 0], c10);
            c11 = fmaf(bq.y, eT[4 * k + 1], c11);
            c12 = fmaf(bq.z, eT[4 * k + 2], c12);
            c13 = fmaf(bq.w, eT[4 * k + 3], c13);
        }
        const float r0 = (c00 + c01) + (c02 + c03);
        const float r1 = (c10 + c11) + (c12 + c13);

        // consume rescale max produced at step t-1 when (t-1)%4 == 0
        float inv0 = 1.f, inv1 = 1.f;
        if (((t - 1) & 3) == 0){
            const float4 q0 = *(const float4*)wmax[0];
            const float4 q1 = *(const float4*)wmax[1];
            const float m0 = fmaxf(fmaxf(q0.x, q0.y), fmaxf(q0.z, q0.w));
            const float m1 = fmaxf(fmaxf(q1.x, q1.y), fmaxf(q1.z, q1.w));
            inv0 = 1.0f / m0;
            inv1 = 1.0f / m1;
            if (j == 0){ lz0 += logf(m0); lz1 += logf(m1); }
        }

        const float v0 = r0 * inv0 * e0;
        const float v1 = r1 * inv1 * e1;

        // produce max for the rescale at step t+1
        if ((t & 3) == 0){
            float m0 = v0, m1 = v1;
            #pragma unroll
            for (int off = 16; off >= 1; off >>= 1){
                m0 = fmaxf(m0, __shfl_xor_sync(0xffffffffu, m0, off));
                m1 = fmaxf(m1, __shfl_xor_sync(0xffffffffu, m1, off));
            }
            if (lane == 0){ wmax[0][w] = m0; wmax[1][w] = m1; }
        }

        alpha[p][0][j] = v0;
        alpha[p][1][j] = v1;
        __syncthreads();
    }

    // partition: log(sum_j alpha_511[j]) + lz, both chains (tid 0)
    if (j == 0){
        double p0 = 0.0, p1 = 0.0;
        for (int i = 0; i < NT; i++){
            p0 += (double)alpha[1][0][i];   // last parity: 511 & 1 = 1
            p1 += (double)alpha[1][1][i];
        }
        atomicAdd(&g_acc, (log(p0) + (double)lz0) + (log(p1) + (double)lz1));
    }
}

extern "C" void kernel_launch(void* const* d_in, const int* in_sizes, int n_in,
                              void* d_out, int out_size)
{
    const float*         emis  = (const float*)d_in[0];
    const void*          tags  = d_in[1];
    const unsigned char* mask  = (const unsigned char*)d_in[2];
    const float*         trans = (const float*)d_in[3];

    zero_acc_kernel<<<1, 1>>>();
    detect_tags_kernel<<<1, 256>>>((const int*)tags);
    gold_kernel<<<(BB * SS) / 256, 256>>>(emis, tags, mask, trans);
    crf_forward<<<BB / 2, 128>>>(emis, trans);
    fin_kernel<<<1, 1>>>((float*)d_out);
}

// round 14
// speedup vs baseline: 1.7539x; 1.1109x over previous
#include <cuda_runtime.h>

#define NT 128
#define BB 256
#define SS 512

__device__ double g_acc;
__device__ int    g_tags_is64;

__global__ void zero_acc_kernel(){ g_acc = 0.0; }
__global__ void fin_kernel(float* out){ out[0] = (float)g_acc; }

// Detect tags dtype: if int64, all high words of valid tags (0..127) are zero.
__global__ void detect_tags_kernel(const int* tags32){
    __shared__ int nz;
    if (threadIdx.x == 0) nz = 0;
    __syncthreads();
    int c = 0;
    for (int k = threadIdx.x; k < 2048; k += 256)
        if (tags32[2 * k + 1] != 0) c = 1;
    if (c) atomicOr(&nz, 1);
    __syncthreads();
    if (threadIdx.x == 0) g_tags_is64 = (nz == 0) ? 1 : 0;
}

__global__ void __launch_bounds__(256) gold_kernel(
    const float* __restrict__ emis, const void* __restrict__ tags_raw,
    const unsigned char* __restrict__ mask, const float* __restrict__ trans)
{
    const int idx = blockIdx.x * 256 + threadIdx.x;
    const int t = idx & (SS - 1);
    const int is64 = g_tags_is64;
    const int* t32 = (const int*)tags_raw;
    const long long* t64 = (const long long*)tags_raw;

    const int tg = is64 ? (int)t64[idx] : t32[idx];
    const float m = mask[idx] ? 1.f : 0.f;
    float v = emis[(size_t)idx * NT + tg] * m;
    if (t > 0){
        const int tp = is64 ? (int)t64[idx - 1] : t32[idx - 1];
        v += trans[tp * NT + tg] * m;
    }
    #pragma unroll
    for (int off = 16; off >= 1; off >>= 1)
        v += __shfl_xor_sync(0xffffffffu, v, off);
    if ((threadIdx.x & 31) == 0)
        atomicAdd(&g_acc, -(double)v);
}

// Forward scan, linear domain + exact periodic rescale.
// 128 blocks x 256 threads. Block = 2 INDEPENDENT chains:
//   half h = tid>>7 (chain b = 2*blk + h), tag j = tid&127.
// Thread j computes the full 128-term dot for its tag (4 ILP chains).
// The two halves share NO data and sync on SEPARATE named barriers, so they
// slip in time against each other: each SMSP hosts one warp of each half
// (warps w and w+4), and while one half sits in its step tail (LDS latency,
// shfl-max, barrier release) the other half's warp issues FMAs.
__global__ void __launch_bounds__(256, 1) crf_forward(
    const float* __restrict__ emis, const float* __restrict__ trans)
{
    __shared__ __align__(16) float alpha[2][2][NT];  // [parity][half][tag]
    __shared__ float wmax[8];                        // warp maxes (0-3 h0, 4-7 h1)

    const int tid  = threadIdx.x;
    const int h    = tid >> 7;
    const int j    = tid & 127;
    const int w    = tid >> 5;          // global warp 0..7
    const int lane = tid & 31;
    const int b    = blockIdx.x * 2 + h;
    const int bar  = 1 + h;             // named barrier id for this half

    // register-cached exp(transitions) column j
    float eT[NT];
    #pragma unroll
    for (int i = 0; i < NT; i++)
        eT[i] = __expf(trans[i * NT + j]);

    const float* eb = emis + (size_t)b * SS * NT + j;

    // t = 0 init
    const float a0 = __expf(eb[0]);
    alpha[0][h][j] = a0;
    {
        float mx = a0;
        #pragma unroll
        for (int off = 16; off >= 1; off >>= 1)
            mx = fmaxf(mx, __shfl_xor_sync(0xffffffffu, mx, off));
        if (lane == 0) wmax[w] = mx;
    }
    float eraw = eb[NT];                // prefetch t = 1
    asm volatile("bar.sync %0, 128;" :: "r"(bar) : "memory");

    float lz = 0.f;                     // uniform within a half

    for (int t = 1; t < SS; t++){
        const int p = t & 1;

        // emission exp off the critical path; branchless clamped prefetch
        const float eexp = __expf(eraw);
        {
            const int tt = (t + 1 < SS) ? (t + 1) : (SS - 1);
            eraw = eb[(size_t)tt * NT];
        }

        // full 128-term dot: 4 independent FMA chains of depth 32
        float c0 = 0.f, c1 = 0.f, c2 = 0.f, c3 = 0.f;
        const float4* ap = (const float4*)alpha[p ^ 1][h];   // broadcast reads
        #pragma unroll
        for (int k = 0; k < NT / 4; k++){
            const float4 a = ap[k];
            c0 = fmaf(a.x, eT[4 * k + 0], c0);
            c1 = fmaf(a.y, eT[4 * k + 1], c1);
            c2 = fmaf(a.z, eT[4 * k + 2], c2);
            c3 = fmaf(a.w, eT[4 * k + 3], c3);
        }
        const float r = (c0 + c1) + (c2 + c3);

        // consume rescale max produced at step t-1 when (t-1)%4 == 0
        float inv = 1.f;
        if (((t - 1) & 3) == 0){
            const float4 q = *(const float4*)(wmax + 4 * h);
            const float m = fmaxf(fmaxf(q.x, q.y), fmaxf(q.z, q.w));
            inv = 1.0f / m;
            lz += logf(m);              // uniform across the half
        }

        const float v = r * inv * eexp;

        // produce max for the rescale at step t+1
        if ((t & 3) == 0){
            float mx = v;
            #pragma unroll
            for (int off = 16; off >= 1; off >>= 1)
                mx = fmaxf(mx, __shfl_xor_sync(0xffffffffu, mx, off));
            if (lane == 0) wmax[w] = mx;
        }

        alpha[p][h][j] = v;
        asm volatile("bar.sync %0, 128;" :: "r"(bar) : "memory");
    }

    // partition: log(sum_j alpha_511[j]) + lz, per half
    if (j == 0){
        double psum = 0.0;
        for (int i = 0; i < NT; i++)
            psum += (double)alpha[1][h][i];   // last parity: 511 & 1 = 1
        atomicAdd(&g_acc, log(psum) + (double)lz);
    }
}

extern "C" void kernel_launch(void* const* d_in, const int* in_sizes, int n_in,
                              void* d_out, int out_size)
{
    const float*         emis  = (const float*)d_in[0];
    const void*          tags  = d_in[1];
    const unsigned char* mask  = (const unsigned char*)d_in[2];
    const float*         trans = (const float*)d_in[3];

    zero_acc_kernel<<<1, 1>>>();
    detect_tags_kernel<<<1, 256>>>((const int*)tags);
    gold_kernel<<<(BB * SS) / 256, 256>>>(emis, tags, mask, trans);
    crf_forward<<<BB / 2, 256>>>(emis, trans);
    fin_kernel<<<1, 1>>>((float*)d_out);
}